// round 13
// baseline (speedup 1.0000x reference)
#include <cuda_runtime.h>
#include <cuda_fp16.h>
#include <math.h>
#include <stdint.h>

#define BB     2
#define HWP    16384
#define CO     128
#define CLI    256
#define CIM    512
#define CHUNKP 2048
#define NCHUNK 8
#define EPSBN  1e-5f
#define SCALE  0.08838834764831845f   // 1/sqrt(128)
#define QSCL   (0.08838834764831845f * 1.4426950408889634f)  // SCALE * log2(e)
#define INVQ   (1.0f / (0.08838834764831845f * 1.4426950408889634f))

__device__ __half g_q16[BB * HWP * CO];   // image proj, pre-scaled by SCALE*log2e
__device__ __half g_k16[BB * HWP * CO];   // lidar proj

// ------------------------------ helpers ------------------------------------
__device__ __forceinline__ uint32_t smem_u32(const void* p) {
    uint32_t a;
    asm("{ .reg .u64 t; cvta.to.shared.u64 t, %1; cvt.u32.u64 %0, t; }" : "=r"(a) : "l"(p));
    return a;
}
__device__ __forceinline__ void mma16816(float* c, const uint32_t* a, const uint32_t* b) {
    asm volatile("mma.sync.aligned.m16n8k16.row.col.f32.f16.f16.f32 "
                 "{%0,%1,%2,%3}, {%4,%5,%6,%7}, {%8,%9}, {%0,%1,%2,%3};"
                 : "+f"(c[0]), "+f"(c[1]), "+f"(c[2]), "+f"(c[3])
                 : "r"(a[0]), "r"(a[1]), "r"(a[2]), "r"(a[3]), "r"(b[0]), "r"(b[1]));
}
__device__ __forceinline__ void ldsm_x4(uint32_t* r, uint32_t a) {
    asm volatile("ldmatrix.sync.aligned.m8n8.x4.shared.b16 {%0,%1,%2,%3}, [%4];"
                 : "=r"(r[0]), "=r"(r[1]), "=r"(r[2]), "=r"(r[3]) : "r"(a));
}
__device__ __forceinline__ void ldsm_x4t(uint32_t* r, uint32_t a) {
    asm volatile("ldmatrix.sync.aligned.m8n8.x4.trans.shared.b16 {%0,%1,%2,%3}, [%4];"
                 : "=r"(r[0]), "=r"(r[1]), "=r"(r[2]), "=r"(r[3]) : "r"(a));
}
__device__ __forceinline__ void ldsm_x2t(uint32_t* r, uint32_t a) {
    asm volatile("ldmatrix.sync.aligned.m8n8.x2.trans.shared.b16 {%0,%1}, [%2];"
                 : "=r"(r[0]), "=r"(r[1]) : "r"(a));
}
__device__ __forceinline__ void cp16(uint32_t dst, const void* src) {
    asm volatile("cp.async.cg.shared.global [%0], [%1], 16;" :: "r"(dst), "l"(src));
}
#define CP_COMMIT() asm volatile("cp.async.commit_group;" ::: "memory")
#define CP_WAIT0()  asm volatile("cp.async.wait_group 0;" ::: "memory")
__device__ __forceinline__ float ex2(float x) {
    float y; asm("ex2.approx.ftz.f32 %0, %1;" : "=f"(y) : "f"(x)); return y;
}

// ------------------- merged fp16 projection kernel (one launch) ------------
// grid (128, BB, 2): z=0 lidar (cin=256, ->k16), z=1 image (cin=512, ->q16)
#define WSOFF 8704
#define PROJ_SMEM (128 * 132 * 4)

__global__ __launch_bounds__(256, 2)
void proj_all_kernel(const float* __restrict__ xl, const float* __restrict__ wl,
                     const float* __restrict__ gl, const float* __restrict__ bl,
                     const float* __restrict__ ml, const float* __restrict__ vl,
                     const float* __restrict__ xi, const float* __restrict__ wi,
                     const float* __restrict__ gi, const float* __restrict__ bi,
                     const float* __restrict__ mi, const float* __restrict__ vi,
                     __half* __restrict__ q16, __half* __restrict__ k16)
{
    extern __shared__ char psm[];
    const uint32_t sbu = smem_u32(psm);
    float* Fs = (float*)psm;
    const int tid = threadIdx.x, wid = tid >> 5, lane = tid & 31;
    const int g = lane >> 2, t4 = lane & 3, l15 = lane & 15;
    const int ob = (wid >> 1) * 32, pb = (wid & 1) * 64;
    const int bb = blockIdx.y, p0 = blockIdx.x * 128;
    const int mod = blockIdx.z;

    const int cin = mod ? CIM : CLI;
    const float* x = mod ? xi : xl;
    const float* w = mod ? wi : wl;
    const float* gamma = mod ? gi : gl;
    const float* beta  = mod ? bi : bl;
    const float* mean  = mod ? mi : ml;
    const float* var   = mod ? vi : vl;
    __half* out16 = mod ? q16 : k16;
    const float hsc = mod ? QSCL : 1.f;

    float acc[2][8][4];
#pragma unroll
    for (int mt = 0; mt < 2; mt++)
#pragma unroll
        for (int nt = 0; nt < 8; nt++)
#pragma unroll
            for (int r = 0; r < 4; r++) acc[mt][nt][r] = 0.f;

    const float* xb = x + (size_t)bb * cin * HWP;
    float4 xr[4];
#pragma unroll
    for (int t = 0; t < 4; t++) {
        int lin = tid + t * 256;
        xr[t] = *(const float4*)&xb[(size_t)(lin >> 5) * HWP + p0 + (lin & 31) * 4];
    }

    for (int c0 = 0; c0 < cin; c0 += 32) {
#pragma unroll
        for (int t = 0; t < 4; t++) {
            int lin = tid + t * 256;
            __half2 h0 = __floats2half2_rn(xr[t].x, xr[t].y);
            __half2 h1 = __floats2half2_rn(xr[t].z, xr[t].w);
            uint2 u; u.x = *(uint32_t*)&h0; u.y = *(uint32_t*)&h1;
            *(uint2*)(psm + (lin >> 5) * 272 + (lin & 31) * 8) = u;
            float4 wv = *(const float4*)&w[(size_t)(lin >> 3) * cin + c0 + (lin & 7) * 4];
            __half2 g0 = __floats2half2_rn(wv.x, wv.y);
            __half2 g1 = __floats2half2_rn(wv.z, wv.w);
            uint2 v; v.x = *(uint32_t*)&g0; v.y = *(uint32_t*)&g1;
            *(uint2*)(psm + WSOFF + (lin >> 3) * 80 + (lin & 7) * 8) = v;
        }
        __syncthreads();
        if (c0 + 32 < cin) {
#pragma unroll
            for (int t = 0; t < 4; t++) {
                int lin = tid + t * 256;
                xr[t] = *(const float4*)&xb[(size_t)(c0 + 32 + (lin >> 5)) * HWP + p0 + (lin & 31) * 4];
            }
        }
#pragma unroll
        for (int ks = 0; ks < 2; ks++) {
            int kc = ks * 16;
            uint32_t a[2][4];
#pragma unroll
            for (int mt = 0; mt < 2; mt++)
                ldsm_x4(a[mt], sbu + WSOFF + (ob + mt * 16 + l15) * 80
                               + (kc + ((lane >> 4) << 3)) * 2);
#pragma unroll
            for (int nt = 0; nt < 8; nt++) {
                uint32_t b[2];
                ldsm_x2t(b, sbu + (kc + l15) * 272 + (pb + nt * 8) * 2);
                mma16816(acc[0][nt], a[0], b);
                mma16816(acc[1][nt], a[1], b);
            }
        }
        __syncthreads();
    }

#pragma unroll
    for (int mt = 0; mt < 2; mt++) {
        int r0 = ob + mt * 16 + g, r1 = r0 + 8;
        float s0 = gamma[r0] * rsqrtf(var[r0] + EPSBN);
        float h0 = beta[r0] - mean[r0] * s0;
        float s1 = gamma[r1] * rsqrtf(var[r1] + EPSBN);
        float h1 = beta[r1] - mean[r1] * s1;
#pragma unroll
        for (int nt = 0; nt < 8; nt++) {
            int p = pb + nt * 8 + 2 * t4;
            Fs[p * 132 + r0]       = fmaxf(fmaf(acc[mt][nt][0], s0, h0), 0.f);
            Fs[(p + 1) * 132 + r0] = fmaxf(fmaf(acc[mt][nt][1], s0, h0), 0.f);
            Fs[p * 132 + r1]       = fmaxf(fmaf(acc[mt][nt][2], s1, h1), 0.f);
            Fs[(p + 1) * 132 + r1] = fmaxf(fmaf(acc[mt][nt][3], s1, h1), 0.f);
        }
    }
    __syncthreads();
#pragma unroll
    for (int t = 0; t < 16; t++) {
        int lin = tid + t * 256, row = lin >> 5, c4 = lin & 31;
        float4 v = *(const float4*)&Fs[row * 132 + c4 * 4];
        size_t base = ((size_t)bb * HWP + p0 + row) * CO + c4 * 4;
        __half2 h0 = __floats2half2_rn(v.x * hsc, v.y * hsc);
        __half2 h1 = __floats2half2_rn(v.z * hsc, v.w * hsc);
        uint2 u; u.x = *(uint32_t*)&h0; u.y = *(uint32_t*)&h1;
        *(uint2*)&out16[base] = u;
    }
}

// ---- FA2 flash attention: pipelined S(i+1) / O(i) / softmax(i+1) ----------
#define NIT   32
#define KB    34816
#define KBUFB 17408
#define ATTN_SMEM (KB + 4 * KBUFB)
#define QLDB  272

__device__ __forceinline__ void fill_k_async(uint32_t sbu, const __half* kb, int buf, int tid) {
    uint32_t kd = sbu + KB + (uint32_t)buf * KBUFB;
#pragma unroll
    for (int t = 0; t < 4; t++) {
        int lin = tid + t * 256;
        int row = lin >> 4, j = lin & 15;
        cp16(kd + row * QLDB + j * 16, kb + (size_t)row * CO + j * 8);
    }
}

__global__ __launch_bounds__(256, 1)
void attn_kernel(const __half* __restrict__ qh, const __half* __restrict__ kh,
                 const float* __restrict__ mw, float* __restrict__ out)
{
    extern __shared__ char smc[];
    const uint32_t sbu = smem_u32(smc);
    const int tid = threadIdx.x, wid = tid >> 5, lane = tid & 31;
    const int g = lane >> 2, t4 = lane & 3;
    const int l15 = lane & 15, l7 = lane & 7;
    const int chunk = blockIdx.y, bb = blockIdx.z;
    const int pq0 = chunk * CHUNKP + blockIdx.x * 128;
    const int mb = wid * 16;

    // async Q + K0 + K1 fills
    const __half* qb = qh + ((size_t)bb * HWP + pq0) * CO;
#pragma unroll
    for (int t = 0; t < 8; t++) {
        int lin = tid + t * 256;
        int row = lin >> 4, j = lin & 15;
        cp16(sbu + row * QLDB + j * 16, qb + (size_t)row * CO + j * 8);
    }
    const __half* ldb = kh + ((size_t)bb * HWP + chunk * CHUNKP) * CO;
    fill_k_async(sbu, ldb, 0, tid);
    fill_k_async(sbu, ldb + (size_t)64 * CO, 1, tid);
    CP_COMMIT();
    CP_WAIT0();
    __syncthreads();

    uint32_t qa[8][4];
#pragma unroll
    for (int ks = 0; ks < 8; ks++)
        ldsm_x4(qa[ks], sbu + (mb + l15) * QLDB + (ks * 16 + ((lane >> 4) << 3)) * 2);
    __syncthreads();

    float oc[16][4];
#pragma unroll
    for (int nt = 0; nt < 16; nt++)
#pragma unroll
        for (int r = 0; r < 4; r++) oc[nt][r] = 0.f;
    float m0 = -3.0e38f, m1 = -3.0e38f, l0 = 0.f, l1 = 0.f;
    float cr0 = 0.f, cr1 = 0.f;
    float sc[8][4];
    uint32_t ph[8][2];

    const uint32_t sbrow = (uint32_t)(l7 + ((lane >> 4) << 3));
    const uint32_t sbcol8 = (uint32_t)(((lane >> 3) & 1) * 8);
    const uint32_t obcol8 = (uint32_t)((lane >> 4) << 3);

    // S-mma into sc from buffer (i&3)
    auto s_mma = [&](int i) {
        const uint32_t kbase = sbu + KB + (uint32_t)(i & 3) * KBUFB;
#pragma unroll
        for (int nt = 0; nt < 8; nt++)
#pragma unroll
            for (int r = 0; r < 4; r++) sc[nt][r] = 0.f;
        uint32_t sB[2][4];
        ldsm_x4(sB[0], kbase + sbrow * QLDB + sbcol8 * 2);
#pragma unroll
        for (int t = 0; t < 32; t++) {
            int ks = t >> 2, ntp = t & 3;
            if (t + 1 < 32) {
                int ks2 = (t + 1) >> 2, ntp2 = (t + 1) & 3;
                ldsm_x4(sB[(t + 1) & 1],
                        kbase + (ntp2 * 16 + sbrow) * QLDB + (ks2 * 16 + sbcol8) * 2);
            }
            mma16816(sc[2 * ntp], qa[ks], sB[t & 1]);
            mma16816(sc[2 * ntp + 1], qa[ks], sB[t & 1] + 2);
        }
    };
    // softmax over sc -> ph, updates m/cr/l
    auto softmax = [&]() {
        float rm0 = -3.0e38f, rm1 = -3.0e38f;
#pragma unroll
        for (int nt = 0; nt < 8; nt++) {
            rm0 = fmaxf(rm0, fmaxf(sc[nt][0], sc[nt][1]));
            rm1 = fmaxf(rm1, fmaxf(sc[nt][2], sc[nt][3]));
        }
        rm0 = fmaxf(rm0, __shfl_xor_sync(0xffffffffu, rm0, 1));
        rm0 = fmaxf(rm0, __shfl_xor_sync(0xffffffffu, rm0, 2));
        rm1 = fmaxf(rm1, __shfl_xor_sync(0xffffffffu, rm1, 1));
        rm1 = fmaxf(rm1, __shfl_xor_sync(0xffffffffu, rm1, 2));
        float mn0 = fmaxf(m0, rm0), mn1 = fmaxf(m1, rm1);
        cr0 = ex2(m0 - mn0); cr1 = ex2(m1 - mn1);
        m0 = mn0; m1 = mn1;
        float ps0 = 0.f, ps1 = 0.f;
#pragma unroll
        for (int nt = 0; nt < 8; nt++) {
            float p0 = ex2(sc[nt][0] - mn0);
            float p1 = ex2(sc[nt][1] - mn0);
            float p2 = ex2(sc[nt][2] - mn1);
            float p3 = ex2(sc[nt][3] - mn1);
            ps0 += p0 + p1; ps1 += p2 + p3;
            __half2 hA = __floats2half2_rn(p0, p1);
            __half2 hB = __floats2half2_rn(p2, p3);
            ph[nt][0] = *(uint32_t*)&hA;
            ph[nt][1] = *(uint32_t*)&hB;
        }
        ps0 += __shfl_xor_sync(0xffffffffu, ps0, 1);
        ps0 += __shfl_xor_sync(0xffffffffu, ps0, 2);
        ps1 += __shfl_xor_sync(0xffffffffu, ps1, 1);
        ps1 += __shfl_xor_sync(0xffffffffu, ps1, 2);
        l0 = l0 * cr0 + ps0;
        l1 = l1 * cr1 + ps1;
    };
    // O rescale + O += P(ph) K(i)
    auto o_mma = [&](int i) {
        const uint32_t kbase = sbu + KB + (uint32_t)(i & 3) * KBUFB;
#pragma unroll
        for (int nt = 0; nt < 16; nt++) {
            oc[nt][0] *= cr0; oc[nt][1] *= cr0;
            oc[nt][2] *= cr1; oc[nt][3] *= cr1;
        }
        uint32_t oB[2][4];
        ldsm_x4t(oB[0], kbase + l15 * QLDB + obcol8 * 2);
#pragma unroll
        for (int t = 0; t < 32; t++) {
            int kq = t >> 3, ntp = t & 7;
            if (t + 1 < 32) {
                int kq2 = (t + 1) >> 3, ntp2 = (t + 1) & 7;
                ldsm_x4t(oB[(t + 1) & 1],
                         kbase + (kq2 * 16 + l15) * QLDB + (ntp2 * 16 + obcol8) * 2);
            }
            uint32_t pa[4] = { ph[2 * kq][0], ph[2 * kq][1],
                               ph[2 * kq + 1][0], ph[2 * kq + 1][1] };
            mma16816(oc[2 * ntp], pa, oB[t & 1]);
            mma16816(oc[2 * ntp + 1], pa, oB[t & 1] + 2);
        }
    };

    // prologue: S(0) + softmax(0) -> ph(0)/cr(0)
    s_mma(0);
    softmax();

    for (int i = 0; i < NIT; i++) {
        if (i + 2 < NIT) {
            fill_k_async(sbu, ldb + (size_t)(i + 2) * 64 * CO, (i + 2) & 3, tid);
            CP_COMMIT();
        }
        if (i + 1 < NIT) s_mma(i + 1);   // tensor: S(i+1) into sc
        o_mma(i);                        // tensor: O(i) using ph(i)/cr(i)
        if (i + 1 < NIT) softmax();      // ALU/MUFU hidden under O(i) drain
        CP_WAIT0();
        __syncthreads();
    }

    // ---- blend epilogue: image reconstructed from qa (q16 / QSCL) ----
    float e0 = __expf(mw[0]), e1 = __expf(mw[1]);
    float w0 = e0 / (e0 + e1), w1 = e1 / (e0 + e1);
    float wq = w0 * INVQ;
    float il0 = 1.f / l0, il1 = 1.f / l1;
    int r0 = mb + g, r1 = mb + 8 + g;
    float* stg = (float*)smc;
    __syncthreads();
#pragma unroll
    for (int nt = 0; nt < 16; nt++) {
        int c = nt * 8 + 2 * t4;
        uint32_t qlo = qa[nt >> 1][(nt & 1) ? 2 : 0];   // row r0, cols c, c+1 (scaled)
        uint32_t qhi = qa[nt >> 1][(nt & 1) ? 3 : 1];   // row r1
        float2 i0 = __half22float2(*(__half2*)&qlo);
        float2 i1 = __half22float2(*(__half2*)&qhi);
        stg[c * 132 + r0]       = wq * i0.x + w1 * oc[nt][0] * il0;
        stg[(c + 1) * 132 + r0] = wq * i0.y + w1 * oc[nt][1] * il0;
        stg[c * 132 + r1]       = wq * i1.x + w1 * oc[nt][2] * il1;
        stg[(c + 1) * 132 + r1] = wq * i1.y + w1 * oc[nt][3] * il1;
    }
    __syncthreads();

    float* ob = out + (size_t)bb * CO * HWP;
#pragma unroll
    for (int t = 0; t < 16; t++) {
        int lin = tid + t * 256;
        int c = lin >> 5, p4 = lin & 31;
        float4 v = *(const float4*)&stg[c * 132 + p4 * 4];
        *(float4*)&ob[(size_t)c * HWP + pq0 + p4 * 4] = v;
    }
}

// ---------------------------------------------------------------------------
extern "C" void kernel_launch(void* const* d_in, const int* in_sizes, int n_in,
                              void* d_out, int out_size)
{
    const float* lidar_x = (const float*)d_in[0];
    const float* image_x = (const float*)d_in[1];
    const float* lw = (const float*)d_in[2];
    const float* lg = (const float*)d_in[3];
    const float* lb = (const float*)d_in[4];
    const float* lm = (const float*)d_in[5];
    const float* lv = (const float*)d_in[6];
    const float* iw = (const float*)d_in[7];
    const float* ig = (const float*)d_in[8];
    const float* ib = (const float*)d_in[9];
    const float* im = (const float*)d_in[10];
    const float* iv = (const float*)d_in[11];
    const float* mw = (const float*)d_in[12];
    float* out = (float*)d_out;

    __half *q16 = nullptr, *k16 = nullptr;
    cudaGetSymbolAddress((void**)&q16, g_q16);
    cudaGetSymbolAddress((void**)&k16, g_k16);
    cudaFuncSetAttribute(proj_all_kernel, cudaFuncAttributeMaxDynamicSharedMemorySize, PROJ_SMEM);
    cudaFuncSetAttribute(attn_kernel, cudaFuncAttributeMaxDynamicSharedMemorySize, ATTN_SMEM);

    dim3 pgrid(HWP / 128, BB, 2);
    proj_all_kernel<<<pgrid, 256, PROJ_SMEM>>>(lidar_x, lw, lg, lb, lm, lv,
                                               image_x, iw, ig, ib, im, iv,
                                               q16, k16);

    dim3 agrid(CHUNKP / 128, NCHUNK, BB);
    attn_kernel<<<agrid, 256, ATTN_SMEM>>>(q16, k16, mw, out);
}

// round 14
// speedup vs baseline: 1.0004x; 1.0004x over previous
#include <cuda_runtime.h>
#include <cuda_fp16.h>
#include <math.h>
#include <stdint.h>

#define BB     2
#define HWP    16384
#define CO     128
#define CLI    256
#define CIM    512
#define CHUNKP 2048
#define NCHUNK 8
#define EPSBN  1e-5f
#define SCALE  0.08838834764831845f   // 1/sqrt(128)
#define QSCL   (0.08838834764831845f * 1.4426950408889634f)  // SCALE * log2(e)
#define INVQ   (1.0f / (0.08838834764831845f * 1.4426950408889634f))

__device__ __half g_q16[BB * HWP * CO];   // image proj, pre-scaled by SCALE*log2e
__device__ __half g_k16[BB * HWP * CO];   // lidar proj

// ------------------------------ helpers ------------------------------------
__device__ __forceinline__ uint32_t smem_u32(const void* p) {
    uint32_t a;
    asm("{ .reg .u64 t; cvta.to.shared.u64 t, %1; cvt.u32.u64 %0, t; }" : "=r"(a) : "l"(p));
    return a;
}
__device__ __forceinline__ void mma16816(float* c, const uint32_t* a, const uint32_t* b) {
    asm volatile("mma.sync.aligned.m16n8k16.row.col.f32.f16.f16.f32 "
                 "{%0,%1,%2,%3}, {%4,%5,%6,%7}, {%8,%9}, {%0,%1,%2,%3};"
                 : "+f"(c[0]), "+f"(c[1]), "+f"(c[2]), "+f"(c[3])
                 : "r"(a[0]), "r"(a[1]), "r"(a[2]), "r"(a[3]), "r"(b[0]), "r"(b[1]));
}
__device__ __forceinline__ void ldsm_x4(uint32_t* r, uint32_t a) {
    asm volatile("ldmatrix.sync.aligned.m8n8.x4.shared.b16 {%0,%1,%2,%3}, [%4];"
                 : "=r"(r[0]), "=r"(r[1]), "=r"(r[2]), "=r"(r[3]) : "r"(a));
}
__device__ __forceinline__ void ldsm_x4t(uint32_t* r, uint32_t a) {
    asm volatile("ldmatrix.sync.aligned.m8n8.x4.trans.shared.b16 {%0,%1,%2,%3}, [%4];"
                 : "=r"(r[0]), "=r"(r[1]), "=r"(r[2]), "=r"(r[3]) : "r"(a));
}
__device__ __forceinline__ void ldsm_x2t(uint32_t* r, uint32_t a) {
    asm volatile("ldmatrix.sync.aligned.m8n8.x2.trans.shared.b16 {%0,%1}, [%2];"
                 : "=r"(r[0]), "=r"(r[1]) : "r"(a));
}
__device__ __forceinline__ void cp16(uint32_t dst, const void* src) {
    asm volatile("cp.async.cg.shared.global [%0], [%1], 16;" :: "r"(dst), "l"(src));
}
#define CP_COMMIT() asm volatile("cp.async.commit_group;" ::: "memory")
#define CP_WAIT0()  asm volatile("cp.async.wait_group 0;" ::: "memory")
__device__ __forceinline__ float ex2(float x) {
    float y; asm("ex2.approx.ftz.f32 %0, %1;" : "=f"(y) : "f"(x)); return y;
}

// ------------------- merged fp16 projection kernel (one launch) ------------
// grid (128, BB, 2): z=0 lidar (cin=256, ->k16), z=1 image (cin=512, ->q16)
#define WSOFF 8704
#define PROJ_SMEM (128 * 132 * 4)

__global__ __launch_bounds__(256, 2)
void proj_all_kernel(const float* __restrict__ xl, const float* __restrict__ wl,
                     const float* __restrict__ gl, const float* __restrict__ bl,
                     const float* __restrict__ ml, const float* __restrict__ vl,
                     const float* __restrict__ xi, const float* __restrict__ wi,
                     const float* __restrict__ gi, const float* __restrict__ bi,
                     const float* __restrict__ mi, const float* __restrict__ vi,
                     __half* __restrict__ q16, __half* __restrict__ k16)
{
    extern __shared__ char psm[];
    const uint32_t sbu = smem_u32(psm);
    float* Fs = (float*)psm;
    const int tid = threadIdx.x, wid = tid >> 5, lane = tid & 31;
    const int g = lane >> 2, t4 = lane & 3, l15 = lane & 15;
    const int ob = (wid >> 1) * 32, pb = (wid & 1) * 64;
    const int bb = blockIdx.y, p0 = blockIdx.x * 128;
    const int mod = blockIdx.z;

    const int cin = mod ? CIM : CLI;
    const float* x = mod ? xi : xl;
    const float* w = mod ? wi : wl;
    const float* gamma = mod ? gi : gl;
    const float* beta  = mod ? bi : bl;
    const float* mean  = mod ? mi : ml;
    const float* var   = mod ? vi : vl;
    __half* out16 = mod ? q16 : k16;
    const float hsc = mod ? QSCL : 1.f;

    float acc[2][8][4];
#pragma unroll
    for (int mt = 0; mt < 2; mt++)
#pragma unroll
        for (int nt = 0; nt < 8; nt++)
#pragma unroll
            for (int r = 0; r < 4; r++) acc[mt][nt][r] = 0.f;

    const float* xb = x + (size_t)bb * cin * HWP;
    float4 xr[4];
#pragma unroll
    for (int t = 0; t < 4; t++) {
        int lin = tid + t * 256;
        xr[t] = *(const float4*)&xb[(size_t)(lin >> 5) * HWP + p0 + (lin & 31) * 4];
    }

    for (int c0 = 0; c0 < cin; c0 += 32) {
#pragma unroll
        for (int t = 0; t < 4; t++) {
            int lin = tid + t * 256;
            __half2 h0 = __floats2half2_rn(xr[t].x, xr[t].y);
            __half2 h1 = __floats2half2_rn(xr[t].z, xr[t].w);
            uint2 u; u.x = *(uint32_t*)&h0; u.y = *(uint32_t*)&h1;
            *(uint2*)(psm + (lin >> 5) * 272 + (lin & 31) * 8) = u;
            float4 wv = *(const float4*)&w[(size_t)(lin >> 3) * cin + c0 + (lin & 7) * 4];
            __half2 g0 = __floats2half2_rn(wv.x, wv.y);
            __half2 g1 = __floats2half2_rn(wv.z, wv.w);
            uint2 v; v.x = *(uint32_t*)&g0; v.y = *(uint32_t*)&g1;
            *(uint2*)(psm + WSOFF + (lin >> 3) * 80 + (lin & 7) * 8) = v;
        }
        __syncthreads();
        if (c0 + 32 < cin) {
#pragma unroll
            for (int t = 0; t < 4; t++) {
                int lin = tid + t * 256;
                xr[t] = *(const float4*)&xb[(size_t)(c0 + 32 + (lin >> 5)) * HWP + p0 + (lin & 31) * 4];
            }
        }
#pragma unroll
        for (int ks = 0; ks < 2; ks++) {
            int kc = ks * 16;
            uint32_t a[2][4];
#pragma unroll
            for (int mt = 0; mt < 2; mt++)
                ldsm_x4(a[mt], sbu + WSOFF + (ob + mt * 16 + l15) * 80
                               + (kc + ((lane >> 4) << 3)) * 2);
#pragma unroll
            for (int nt = 0; nt < 8; nt++) {
                uint32_t b[2];
                ldsm_x2t(b, sbu + (kc + l15) * 272 + (pb + nt * 8) * 2);
                mma16816(acc[0][nt], a[0], b);
                mma16816(acc[1][nt], a[1], b);
            }
        }
        __syncthreads();
    }

#pragma unroll
    for (int mt = 0; mt < 2; mt++) {
        int r0 = ob + mt * 16 + g, r1 = r0 + 8;
        float s0 = gamma[r0] * rsqrtf(var[r0] + EPSBN);
        float h0 = beta[r0] - mean[r0] * s0;
        float s1 = gamma[r1] * rsqrtf(var[r1] + EPSBN);
        float h1 = beta[r1] - mean[r1] * s1;
#pragma unroll
        for (int nt = 0; nt < 8; nt++) {
            int p = pb + nt * 8 + 2 * t4;
            Fs[p * 132 + r0]       = fmaxf(fmaf(acc[mt][nt][0], s0, h0), 0.f);
            Fs[(p + 1) * 132 + r0] = fmaxf(fmaf(acc[mt][nt][1], s0, h0), 0.f);
            Fs[p * 132 + r1]       = fmaxf(fmaf(acc[mt][nt][2], s1, h1), 0.f);
            Fs[(p + 1) * 132 + r1] = fmaxf(fmaf(acc[mt][nt][3], s1, h1), 0.f);
        }
    }
    __syncthreads();
#pragma unroll
    for (int t = 0; t < 16; t++) {
        int lin = tid + t * 256, row = lin >> 5, c4 = lin & 31;
        float4 v = *(const float4*)&Fs[row * 132 + c4 * 4];
        size_t base = ((size_t)bb * HWP + p0 + row) * CO + c4 * 4;
        __half2 h0 = __floats2half2_rn(v.x * hsc, v.y * hsc);
        __half2 h1 = __floats2half2_rn(v.z * hsc, v.w * hsc);
        uint2 u; u.x = *(uint32_t*)&h0; u.y = *(uint32_t*)&h1;
        *(uint2*)&out16[base] = u;
    }
}

// ---- FA2 flash attention: pipelined S(i+1) / O(i) / softmax(i+1) ----------
#define NIT   32
#define KB    34816
#define KBUFB 17408
#define ATTN_SMEM (KB + 4 * KBUFB)
#define QLDB  272

__device__ __forceinline__ void fill_k_async(uint32_t sbu, const __half* kb, int buf, int tid) {
    uint32_t kd = sbu + KB + (uint32_t)buf * KBUFB;
#pragma unroll
    for (int t = 0; t < 4; t++) {
        int lin = tid + t * 256;
        int row = lin >> 4, j = lin & 15;
        cp16(kd + row * QLDB + j * 16, kb + (size_t)row * CO + j * 8);
    }
}

__global__ __launch_bounds__(256, 1)
void attn_kernel(const __half* __restrict__ qh, const __half* __restrict__ kh,
                 const float* __restrict__ mw, float* __restrict__ out)
{
    extern __shared__ char smc[];
    const uint32_t sbu = smem_u32(smc);
    const int tid = threadIdx.x, wid = tid >> 5, lane = tid & 31;
    const int g = lane >> 2, t4 = lane & 3;
    const int l15 = lane & 15, l7 = lane & 7;
    const int chunk = blockIdx.y, bb = blockIdx.z;
    const int pq0 = chunk * CHUNKP + blockIdx.x * 128;
    const int mb = wid * 16;

    // async Q + K0 + K1 fills
    const __half* qb = qh + ((size_t)bb * HWP + pq0) * CO;
#pragma unroll
    for (int t = 0; t < 8; t++) {
        int lin = tid + t * 256;
        int row = lin >> 4, j = lin & 15;
        cp16(sbu + row * QLDB + j * 16, qb + (size_t)row * CO + j * 8);
    }
    const __half* ldb = kh + ((size_t)bb * HWP + chunk * CHUNKP) * CO;
    fill_k_async(sbu, ldb, 0, tid);
    fill_k_async(sbu, ldb + (size_t)64 * CO, 1, tid);
    CP_COMMIT();
    CP_WAIT0();
    __syncthreads();

    uint32_t qa[8][4];
#pragma unroll
    for (int ks = 0; ks < 8; ks++)
        ldsm_x4(qa[ks], sbu + (mb + l15) * QLDB + (ks * 16 + ((lane >> 4) << 3)) * 2);
    __syncthreads();

    float oc[16][4];
#pragma unroll
    for (int nt = 0; nt < 16; nt++)
#pragma unroll
        for (int r = 0; r < 4; r++) oc[nt][r] = 0.f;
    float m0 = -3.0e38f, m1 = -3.0e38f, l0 = 0.f, l1 = 0.f;
    float cr0 = 0.f, cr1 = 0.f;
    float sc[8][4];
    uint32_t ph[8][2];

    const uint32_t sbrow = (uint32_t)(l7 + ((lane >> 4) << 3));
    const uint32_t sbcol8 = (uint32_t)(((lane >> 3) & 1) * 8);
    const uint32_t obcol8 = (uint32_t)((lane >> 4) << 3);

    // S-mma into sc from buffer (i&3)
    auto s_mma = [&](int i) {
        const uint32_t kbase = sbu + KB + (uint32_t)(i & 3) * KBUFB;
#pragma unroll
        for (int nt = 0; nt < 8; nt++)
#pragma unroll
            for (int r = 0; r < 4; r++) sc[nt][r] = 0.f;
        uint32_t sB[2][4];
        ldsm_x4(sB[0], kbase + sbrow * QLDB + sbcol8 * 2);
#pragma unroll
        for (int t = 0; t < 32; t++) {
            int ks = t >> 2, ntp = t & 3;
            if (t + 1 < 32) {
                int ks2 = (t + 1) >> 2, ntp2 = (t + 1) & 3;
                ldsm_x4(sB[(t + 1) & 1],
                        kbase + (ntp2 * 16 + sbrow) * QLDB + (ks2 * 16 + sbcol8) * 2);
            }
            mma16816(sc[2 * ntp], qa[ks], sB[t & 1]);
            mma16816(sc[2 * ntp + 1], qa[ks], sB[t & 1] + 2);
        }
    };
    // softmax over sc -> ph, updates m/cr/l
    auto softmax = [&]() {
        float rm0 = -3.0e38f, rm1 = -3.0e38f;
#pragma unroll
        for (int nt = 0; nt < 8; nt++) {
            rm0 = fmaxf(rm0, fmaxf(sc[nt][0], sc[nt][1]));
            rm1 = fmaxf(rm1, fmaxf(sc[nt][2], sc[nt][3]));
        }
        rm0 = fmaxf(rm0, __shfl_xor_sync(0xffffffffu, rm0, 1));
        rm0 = fmaxf(rm0, __shfl_xor_sync(0xffffffffu, rm0, 2));
        rm1 = fmaxf(rm1, __shfl_xor_sync(0xffffffffu, rm1, 1));
        rm1 = fmaxf(rm1, __shfl_xor_sync(0xffffffffu, rm1, 2));
        float mn0 = fmaxf(m0, rm0), mn1 = fmaxf(m1, rm1);
        cr0 = ex2(m0 - mn0); cr1 = ex2(m1 - mn1);
        m0 = mn0; m1 = mn1;
        float ps0 = 0.f, ps1 = 0.f;
#pragma unroll
        for (int nt = 0; nt < 8; nt++) {
            float p0 = ex2(sc[nt][0] - mn0);
            float p1 = ex2(sc[nt][1] - mn0);
            float p2 = ex2(sc[nt][2] - mn1);
            float p3 = ex2(sc[nt][3] - mn1);
            ps0 += p0 + p1; ps1 += p2 + p3;
            __half2 hA = __floats2half2_rn(p0, p1);
            __half2 hB = __floats2half2_rn(p2, p3);
            ph[nt][0] = *(uint32_t*)&hA;
            ph[nt][1] = *(uint32_t*)&hB;
        }
        ps0 += __shfl_xor_sync(0xffffffffu, ps0, 1);
        ps0 += __shfl_xor_sync(0xffffffffu, ps0, 2);
        ps1 += __shfl_xor_sync(0xffffffffu, ps1, 1);
        ps1 += __shfl_xor_sync(0xffffffffu, ps1, 2);
        l0 = l0 * cr0 + ps0;
        l1 = l1 * cr1 + ps1;
    };
    // O rescale + O += P(ph) K(i)
    auto o_mma = [&](int i) {
        const uint32_t kbase = sbu + KB + (uint32_t)(i & 3) * KBUFB;
#pragma unroll
        for (int nt = 0; nt < 16; nt++) {
            oc[nt][0] *= cr0; oc[nt][1] *= cr0;
            oc[nt][2] *= cr1; oc[nt][3] *= cr1;
        }
        uint32_t oB[2][4];
        ldsm_x4t(oB[0], kbase + l15 * QLDB + obcol8 * 2);
#pragma unroll
        for (int t = 0; t < 32; t++) {
            int kq = t >> 3, ntp = t & 7;
            if (t + 1 < 32) {
                int kq2 = (t + 1) >> 3, ntp2 = (t + 1) & 7;
                ldsm_x4t(oB[(t + 1) & 1],
                         kbase + (kq2 * 16 + l15) * QLDB + (ntp2 * 16 + obcol8) * 2);
            }
            uint32_t pa[4] = { ph[2 * kq][0], ph[2 * kq][1],
                               ph[2 * kq + 1][0], ph[2 * kq + 1][1] };
            mma16816(oc[2 * ntp], pa, oB[t & 1]);
            mma16816(oc[2 * ntp + 1], pa, oB[t & 1] + 2);
        }
    };

    // prologue: S(0) + softmax(0) -> ph(0)/cr(0)
    s_mma(0);
    softmax();

    for (int i = 0; i < NIT; i++) {
        if (i + 2 < NIT) {
            fill_k_async(sbu, ldb + (size_t)(i + 2) * 64 * CO, (i + 2) & 3, tid);
            CP_COMMIT();
        }
        if (i + 1 < NIT) s_mma(i + 1);   // tensor: S(i+1) into sc
        o_mma(i);                        // tensor: O(i) using ph(i)/cr(i)
        if (i + 1 < NIT) softmax();      // ALU/MUFU hidden under O(i) drain
        CP_WAIT0();
        __syncthreads();
    }

    // ---- blend epilogue: image reconstructed from qa (q16 / QSCL) ----
    float e0 = __expf(mw[0]), e1 = __expf(mw[1]);
    float w0 = e0 / (e0 + e1), w1 = e1 / (e0 + e1);
    float wq = w0 * INVQ;
    float il0 = 1.f / l0, il1 = 1.f / l1;
    int r0 = mb + g, r1 = mb + 8 + g;
    float* stg = (float*)smc;
    __syncthreads();
#pragma unroll
    for (int nt = 0; nt < 16; nt++) {
        int c = nt * 8 + 2 * t4;
        uint32_t qlo = qa[nt >> 1][(nt & 1) ? 2 : 0];   // row r0, cols c, c+1 (scaled)
        uint32_t qhi = qa[nt >> 1][(nt & 1) ? 3 : 1];   // row r1
        float2 i0 = __half22float2(*(__half2*)&qlo);
        float2 i1 = __half22float2(*(__half2*)&qhi);
        stg[c * 132 + r0]       = wq * i0.x + w1 * oc[nt][0] * il0;
        stg[(c + 1) * 132 + r0] = wq * i0.y + w1 * oc[nt][1] * il0;
        stg[c * 132 + r1]       = wq * i1.x + w1 * oc[nt][2] * il1;
        stg[(c + 1) * 132 + r1] = wq * i1.y + w1 * oc[nt][3] * il1;
    }
    __syncthreads();

    float* ob = out + (size_t)bb * CO * HWP;
#pragma unroll
    for (int t = 0; t < 16; t++) {
        int lin = tid + t * 256;
        int c = lin >> 5, p4 = lin & 31;
        float4 v = *(const float4*)&stg[c * 132 + p4 * 4];
        *(float4*)&ob[(size_t)c * HWP + pq0 + p4 * 4] = v;
    }
}

// ---------------------------------------------------------------------------
extern "C" void kernel_launch(void* const* d_in, const int* in_sizes, int n_in,
                              void* d_out, int out_size)
{
    const float* lidar_x = (const float*)d_in[0];
    const float* image_x = (const float*)d_in[1];
    const float* lw = (const float*)d_in[2];
    const float* lg = (const float*)d_in[3];
    const float* lb = (const float*)d_in[4];
    const float* lm = (const float*)d_in[5];
    const float* lv = (const float*)d_in[6];
    const float* iw = (const float*)d_in[7];
    const float* ig = (const float*)d_in[8];
    const float* ib = (const float*)d_in[9];
    const float* im = (const float*)d_in[10];
    const float* iv = (const float*)d_in[11];
    const float* mw = (const float*)d_in[12];
    float* out = (float*)d_out;

    __half *q16 = nullptr, *k16 = nullptr;
    cudaGetSymbolAddress((void**)&q16, g_q16);
    cudaGetSymbolAddress((void**)&k16, g_k16);
    cudaFuncSetAttribute(proj_all_kernel, cudaFuncAttributeMaxDynamicSharedMemorySize, PROJ_SMEM);
    cudaFuncSetAttribute(attn_kernel, cudaFuncAttributeMaxDynamicSharedMemorySize, ATTN_SMEM);

    dim3 pgrid(HWP / 128, BB, 2);
    proj_all_kernel<<<pgrid, 256, PROJ_SMEM>>>(lidar_x, lw, lg, lb, lm, lv,
                                               image_x, iw, ig, ib, im, iv,
                                               q16, k16);

    dim3 agrid(CHUNKP / 128, NCHUNK, BB);
    attn_kernel<<<agrid, 256, ATTN_SMEM>>>(q16, k16, mw, out);
}

// round 15
// speedup vs baseline: 1.1320x; 1.1316x over previous
#include <cuda_runtime.h>
#include <cuda_fp16.h>
#include <math.h>
#include <stdint.h>

#define BB     2
#define HWP    16384
#define CO     128
#define CLI    256
#define CIM    512
#define CHUNKP 2048
#define NCHUNK 8
#define EPSBN  1e-5f
#define SCALE  0.08838834764831845f   // 1/sqrt(128)
#define QSCL   (0.08838834764831845f * 1.4426950408889634f)  // SCALE * log2(e)
#define INVQ   (1.0f / (0.08838834764831845f * 1.4426950408889634f))

__device__ __half g_q16[BB * HWP * CO];   // image proj, pre-scaled by SCALE*log2e
__device__ __half g_k16[BB * HWP * CO];   // lidar proj

// ------------------------------ helpers ------------------------------------
__device__ __forceinline__ uint32_t smem_u32(const void* p) {
    uint32_t a;
    asm("{ .reg .u64 t; cvta.to.shared.u64 t, %1; cvt.u32.u64 %0, t; }" : "=r"(a) : "l"(p));
    return a;
}
__device__ __forceinline__ void mma16816(float* c, const uint32_t* a, const uint32_t* b) {
    asm volatile("mma.sync.aligned.m16n8k16.row.col.f32.f16.f16.f32 "
                 "{%0,%1,%2,%3}, {%4,%5,%6,%7}, {%8,%9}, {%0,%1,%2,%3};"
                 : "+f"(c[0]), "+f"(c[1]), "+f"(c[2]), "+f"(c[3])
                 : "r"(a[0]), "r"(a[1]), "r"(a[2]), "r"(a[3]), "r"(b[0]), "r"(b[1]));
}
__device__ __forceinline__ void ldsm_x4(uint32_t* r, uint32_t a) {
    asm volatile("ldmatrix.sync.aligned.m8n8.x4.shared.b16 {%0,%1,%2,%3}, [%4];"
                 : "=r"(r[0]), "=r"(r[1]), "=r"(r[2]), "=r"(r[3]) : "r"(a));
}
__device__ __forceinline__ void ldsm_x4t(uint32_t* r, uint32_t a) {
    asm volatile("ldmatrix.sync.aligned.m8n8.x4.trans.shared.b16 {%0,%1,%2,%3}, [%4];"
                 : "=r"(r[0]), "=r"(r[1]), "=r"(r[2]), "=r"(r[3]) : "r"(a));
}
__device__ __forceinline__ void ldsm_x2t(uint32_t* r, uint32_t a) {
    asm volatile("ldmatrix.sync.aligned.m8n8.x2.trans.shared.b16 {%0,%1}, [%2];"
                 : "=r"(r[0]), "=r"(r[1]) : "r"(a));
}
__device__ __forceinline__ void cp16(uint32_t dst, const void* src) {
    asm volatile("cp.async.cg.shared.global [%0], [%1], 16;" :: "r"(dst), "l"(src));
}
#define CP_COMMIT() asm volatile("cp.async.commit_group;" ::: "memory")
#define CP_WAIT0()  asm volatile("cp.async.wait_group 0;" ::: "memory")
__device__ __forceinline__ float ex2(float x) {
    float y; asm("ex2.approx.ftz.f32 %0, %1;" : "=f"(y) : "f"(x)); return y;
}

// ------------------- merged fp16 projection kernel (one launch) ------------
// grid (128, BB, 2): z=0 lidar (cin=256, ->k16), z=1 image (cin=512, ->q16)
#define WSOFF 8704
#define PROJ_SMEM (128 * 132 * 4)

__global__ __launch_bounds__(256, 2)
void proj_all_kernel(const float* __restrict__ xl, const float* __restrict__ wl,
                     const float* __restrict__ gl, const float* __restrict__ bl,
                     const float* __restrict__ ml, const float* __restrict__ vl,
                     const float* __restrict__ xi, const float* __restrict__ wi,
                     const float* __restrict__ gi, const float* __restrict__ bi,
                     const float* __restrict__ mi, const float* __restrict__ vi,
                     __half* __restrict__ q16, __half* __restrict__ k16)
{
    extern __shared__ char psm[];
    const uint32_t sbu = smem_u32(psm);
    float* Fs = (float*)psm;
    const int tid = threadIdx.x, wid = tid >> 5, lane = tid & 31;
    const int g = lane >> 2, t4 = lane & 3, l15 = lane & 15;
    const int ob = (wid >> 1) * 32, pb = (wid & 1) * 64;
    const int bb = blockIdx.y, p0 = blockIdx.x * 128;
    const int mod = blockIdx.z;

    const int cin = mod ? CIM : CLI;
    const float* x = mod ? xi : xl;
    const float* w = mod ? wi : wl;
    const float* gamma = mod ? gi : gl;
    const float* beta  = mod ? bi : bl;
    const float* mean  = mod ? mi : ml;
    const float* var   = mod ? vi : vl;
    __half* out16 = mod ? q16 : k16;
    const float hsc = mod ? QSCL : 1.f;

    float acc[2][8][4];
#pragma unroll
    for (int mt = 0; mt < 2; mt++)
#pragma unroll
        for (int nt = 0; nt < 8; nt++)
#pragma unroll
            for (int r = 0; r < 4; r++) acc[mt][nt][r] = 0.f;

    const float* xb = x + (size_t)bb * cin * HWP;
    float4 xr[4];
#pragma unroll
    for (int t = 0; t < 4; t++) {
        int lin = tid + t * 256;
        xr[t] = *(const float4*)&xb[(size_t)(lin >> 5) * HWP + p0 + (lin & 31) * 4];
    }

    for (int c0 = 0; c0 < cin; c0 += 32) {
#pragma unroll
        for (int t = 0; t < 4; t++) {
            int lin = tid + t * 256;
            __half2 h0 = __floats2half2_rn(xr[t].x, xr[t].y);
            __half2 h1 = __floats2half2_rn(xr[t].z, xr[t].w);
            uint2 u; u.x = *(uint32_t*)&h0; u.y = *(uint32_t*)&h1;
            *(uint2*)(psm + (lin >> 5) * 272 + (lin & 31) * 8) = u;
            float4 wv = *(const float4*)&w[(size_t)(lin >> 3) * cin + c0 + (lin & 7) * 4];
            __half2 g0 = __floats2half2_rn(wv.x, wv.y);
            __half2 g1 = __floats2half2_rn(wv.z, wv.w);
            uint2 v; v.x = *(uint32_t*)&g0; v.y = *(uint32_t*)&g1;
            *(uint2*)(psm + WSOFF + (lin >> 3) * 80 + (lin & 7) * 8) = v;
        }
        __syncthreads();
        if (c0 + 32 < cin) {
#pragma unroll
            for (int t = 0; t < 4; t++) {
                int lin = tid + t * 256;
                xr[t] = *(const float4*)&xb[(size_t)(c0 + 32 + (lin >> 5)) * HWP + p0 + (lin & 31) * 4];
            }
        }
#pragma unroll
        for (int ks = 0; ks < 2; ks++) {
            int kc = ks * 16;
            uint32_t a[2][4];
#pragma unroll
            for (int mt = 0; mt < 2; mt++)
                ldsm_x4(a[mt], sbu + WSOFF + (ob + mt * 16 + l15) * 80
                               + (kc + ((lane >> 4) << 3)) * 2);
#pragma unroll
            for (int nt = 0; nt < 8; nt++) {
                uint32_t b[2];
                ldsm_x2t(b, sbu + (kc + l15) * 272 + (pb + nt * 8) * 2);
                mma16816(acc[0][nt], a[0], b);
                mma16816(acc[1][nt], a[1], b);
            }
        }
        __syncthreads();
    }

#pragma unroll
    for (int mt = 0; mt < 2; mt++) {
        int r0 = ob + mt * 16 + g, r1 = r0 + 8;
        float s0 = gamma[r0] * rsqrtf(var[r0] + EPSBN);
        float h0 = beta[r0] - mean[r0] * s0;
        float s1 = gamma[r1] * rsqrtf(var[r1] + EPSBN);
        float h1 = beta[r1] - mean[r1] * s1;
#pragma unroll
        for (int nt = 0; nt < 8; nt++) {
            int p = pb + nt * 8 + 2 * t4;
            Fs[p * 132 + r0]       = fmaxf(fmaf(acc[mt][nt][0], s0, h0), 0.f);
            Fs[(p + 1) * 132 + r0] = fmaxf(fmaf(acc[mt][nt][1], s0, h0), 0.f);
            Fs[p * 132 + r1]       = fmaxf(fmaf(acc[mt][nt][2], s1, h1), 0.f);
            Fs[(p + 1) * 132 + r1] = fmaxf(fmaf(acc[mt][nt][3], s1, h1), 0.f);
        }
    }
    __syncthreads();
#pragma unroll
    for (int t = 0; t < 16; t++) {
        int lin = tid + t * 256, row = lin >> 5, c4 = lin & 31;
        float4 v = *(const float4*)&Fs[row * 132 + c4 * 4];
        size_t base = ((size_t)bb * HWP + p0 + row) * CO + c4 * 4;
        __half2 h0 = __floats2half2_rn(v.x * hsc, v.y * hsc);
        __half2 h1 = __floats2half2_rn(v.z * hsc, v.w * hsc);
        uint2 u; u.x = *(uint32_t*)&h0; u.y = *(uint32_t*)&h1;
        *(uint2*)&out16[base] = u;
    }
}

// ---- FA2 flash attention (R12 loop: 2 iters/barrier; qa-register blend) ---
#define NIT   32
#define KB    34816
#define KBUFB 17408
#define ATTN_SMEM (KB + 4 * KBUFB)
#define QLDB  272

__device__ __forceinline__ void fill_k_async(uint32_t sbu, const __half* kb, int buf, int tid) {
    uint32_t kd = sbu + KB + (uint32_t)buf * KBUFB;
#pragma unroll
    for (int t = 0; t < 4; t++) {
        int lin = tid + t * 256;
        int row = lin >> 4, j = lin & 15;
        cp16(kd + row * QLDB + j * 16, kb + (size_t)row * CO + j * 8);
    }
}

__global__ __launch_bounds__(256, 1)
void attn_kernel(const __half* __restrict__ qh, const __half* __restrict__ kh,
                 const float* __restrict__ mw, float* __restrict__ out)
{
    extern __shared__ char smc[];
    const uint32_t sbu = smem_u32(smc);
    const int tid = threadIdx.x, wid = tid >> 5, lane = tid & 31;
    const int g = lane >> 2, t4 = lane & 3;
    const int l15 = lane & 15, l7 = lane & 7;
    const int chunk = blockIdx.y, bb = blockIdx.z;
    const int pq0 = chunk * CHUNKP + blockIdx.x * 128;
    const int mb = wid * 16;

    // async Q + K0 + K1 fills
    const __half* qb = qh + ((size_t)bb * HWP + pq0) * CO;
#pragma unroll
    for (int t = 0; t < 8; t++) {
        int lin = tid + t * 256;
        int row = lin >> 4, j = lin & 15;
        cp16(sbu + row * QLDB + j * 16, qb + (size_t)row * CO + j * 8);
    }
    const __half* ldb = kh + ((size_t)bb * HWP + chunk * CHUNKP) * CO;
    fill_k_async(sbu, ldb, 0, tid);
    fill_k_async(sbu, ldb + (size_t)64 * CO, 1, tid);
    CP_COMMIT();
    CP_WAIT0();
    __syncthreads();

    uint32_t qa[8][4];
#pragma unroll
    for (int ks = 0; ks < 8; ks++)
        ldsm_x4(qa[ks], sbu + (mb + l15) * QLDB + (ks * 16 + ((lane >> 4) << 3)) * 2);
    __syncthreads();

    float oc[16][4];
#pragma unroll
    for (int nt = 0; nt < 16; nt++)
#pragma unroll
        for (int r = 0; r < 4; r++) oc[nt][r] = 0.f;
    float m0 = -3.0e38f, m1 = -3.0e38f, l0 = 0.f, l1 = 0.f;

    const uint32_t sbrow = (uint32_t)(l7 + ((lane >> 4) << 3));
    const uint32_t sbcol8 = (uint32_t)(((lane >> 3) & 1) * 8);
    const uint32_t obcol8 = (uint32_t)((lane >> 4) << 3);

    auto compute = [&](int i) {
        const uint32_t kbase = sbu + KB + (uint32_t)(i & 3) * KBUFB;

        // ---- S = Q K^T, pipelined B loads ----
        float sc[8][4];
#pragma unroll
        for (int nt = 0; nt < 8; nt++)
#pragma unroll
            for (int r = 0; r < 4; r++) sc[nt][r] = 0.f;

        uint32_t sB[2][4];
        ldsm_x4(sB[0], kbase + sbrow * QLDB + sbcol8 * 2);
#pragma unroll
        for (int t = 0; t < 32; t++) {
            int ks = t >> 2, ntp = t & 3;
            if (t + 1 < 32) {
                int ks2 = (t + 1) >> 2, ntp2 = (t + 1) & 3;
                ldsm_x4(sB[(t + 1) & 1],
                        kbase + (ntp2 * 16 + sbrow) * QLDB + (ks2 * 16 + sbcol8) * 2);
            }
            mma16816(sc[2 * ntp], qa[ks], sB[t & 1]);
            mma16816(sc[2 * ntp + 1], qa[ks], sB[t & 1] + 2);
        }

        // ---- softmax (rows mb+g, mb+8+g), log2 domain ----
        float rm0 = -3.0e38f, rm1 = -3.0e38f;
#pragma unroll
        for (int nt = 0; nt < 8; nt++) {
            rm0 = fmaxf(rm0, fmaxf(sc[nt][0], sc[nt][1]));
            rm1 = fmaxf(rm1, fmaxf(sc[nt][2], sc[nt][3]));
        }
        rm0 = fmaxf(rm0, __shfl_xor_sync(0xffffffffu, rm0, 1));
        rm0 = fmaxf(rm0, __shfl_xor_sync(0xffffffffu, rm0, 2));
        rm1 = fmaxf(rm1, __shfl_xor_sync(0xffffffffu, rm1, 1));
        rm1 = fmaxf(rm1, __shfl_xor_sync(0xffffffffu, rm1, 2));
        float mn0 = fmaxf(m0, rm0), mn1 = fmaxf(m1, rm1);
        float cr0 = ex2(m0 - mn0), cr1 = ex2(m1 - mn1);
        m0 = mn0; m1 = mn1;

        uint32_t ph[8][2];
        float ps0 = 0.f, ps1 = 0.f;
#pragma unroll
        for (int nt = 0; nt < 8; nt++) {
            float p0 = ex2(sc[nt][0] - mn0);
            float p1 = ex2(sc[nt][1] - mn0);
            float p2 = ex2(sc[nt][2] - mn1);
            float p3 = ex2(sc[nt][3] - mn1);
            ps0 += p0 + p1; ps1 += p2 + p3;
            __half2 hA = __floats2half2_rn(p0, p1);
            __half2 hB = __floats2half2_rn(p2, p3);
            ph[nt][0] = *(uint32_t*)&hA;
            ph[nt][1] = *(uint32_t*)&hB;
        }
        ps0 += __shfl_xor_sync(0xffffffffu, ps0, 1);
        ps0 += __shfl_xor_sync(0xffffffffu, ps0, 2);
        ps1 += __shfl_xor_sync(0xffffffffu, ps1, 1);
        ps1 += __shfl_xor_sync(0xffffffffu, ps1, 2);
        l0 = l0 * cr0 + ps0;
        l1 = l1 * cr1 + ps1;

        // ---- O rescale + O += P K, pipelined B loads ----
#pragma unroll
        for (int nt = 0; nt < 16; nt++) {
            oc[nt][0] *= cr0; oc[nt][1] *= cr0;
            oc[nt][2] *= cr1; oc[nt][3] *= cr1;
        }
        uint32_t oB[2][4];
        ldsm_x4t(oB[0], kbase + l15 * QLDB + obcol8 * 2);
#pragma unroll
        for (int t = 0; t < 32; t++) {
            int kq = t >> 3, ntp = t & 7;
            if (t + 1 < 32) {
                int kq2 = (t + 1) >> 3, ntp2 = (t + 1) & 7;
                ldsm_x4t(oB[(t + 1) & 1],
                         kbase + (kq2 * 16 + l15) * QLDB + (ntp2 * 16 + obcol8) * 2);
            }
            uint32_t pa[4] = { ph[2 * kq][0], ph[2 * kq][1],
                               ph[2 * kq + 1][0], ph[2 * kq + 1][1] };
            mma16816(oc[2 * ntp], pa, oB[t & 1]);
            mma16816(oc[2 * ntp + 1], pa, oB[t & 1] + 2);
        }
    };

    for (int i = 0; i < NIT; i += 2) {
        if (i + 2 < NIT) fill_k_async(sbu, ldb + (size_t)(i + 2) * 64 * CO, (i + 2) & 3, tid);
        if (i + 3 < NIT) fill_k_async(sbu, ldb + (size_t)(i + 3) * 64 * CO, (i + 3) & 3, tid);
        CP_COMMIT();
        compute(i);
        compute(i + 1);
        CP_WAIT0();
        __syncthreads();
    }

    // ---- blend epilogue: image reconstructed from qa (q16 / QSCL) ----
    float e0 = __expf(mw[0]), e1 = __expf(mw[1]);
    float w0 = e0 / (e0 + e1), w1 = e1 / (e0 + e1);
    float wq = w0 * INVQ;
    float il0 = 1.f / l0, il1 = 1.f / l1;
    int r0 = mb + g, r1 = mb + 8 + g;
    float* stg = (float*)smc;
    __syncthreads();
#pragma unroll
    for (int nt = 0; nt < 16; nt++) {
        int c = nt * 8 + 2 * t4;
        uint32_t qlo = qa[nt >> 1][(nt & 1) ? 2 : 0];   // row r0, cols c, c+1 (scaled)
        uint32_t qhi = qa[nt >> 1][(nt & 1) ? 3 : 1];   // row r1
        float2 i0 = __half22float2(*(__half2*)&qlo);
        float2 i1 = __half22float2(*(__half2*)&qhi);
        stg[c * 132 + r0]       = wq * i0.x + w1 * oc[nt][0] * il0;
        stg[(c + 1) * 132 + r0] = wq * i0.y + w1 * oc[nt][1] * il0;
        stg[c * 132 + r1]       = wq * i1.x + w1 * oc[nt][2] * il1;
        stg[(c + 1) * 132 + r1] = wq * i1.y + w1 * oc[nt][3] * il1;
    }
    __syncthreads();

    float* ob = out + (size_t)bb * CO * HWP;
#pragma unroll
    for (int t = 0; t < 16; t++) {
        int lin = tid + t * 256;
        int c = lin >> 5, p4 = lin & 31;
        float4 v = *(const float4*)&stg[c * 132 + p4 * 4];
        *(float4*)&ob[(size_t)c * HWP + pq0 + p4 * 4] = v;
    }
}

// ---------------------------------------------------------------------------
extern "C" void kernel_launch(void* const* d_in, const int* in_sizes, int n_in,
                              void* d_out, int out_size)
{
    const float* lidar_x = (const float*)d_in[0];
    const float* image_x = (const float*)d_in[1];
    const float* lw = (const float*)d_in[2];
    const float* lg = (const float*)d_in[3];
    const float* lb = (const float*)d_in[4];
    const float* lm = (const float*)d_in[5];
    const float* lv = (const float*)d_in[6];
    const float* iw = (const float*)d_in[7];
    const float* ig = (const float*)d_in[8];
    const float* ib = (const float*)d_in[9];
    const float* im = (const float*)d_in[10];
    const float* iv = (const float*)d_in[11];
    const float* mw = (const float*)d_in[12];
    float* out = (float*)d_out;

    __half *q16 = nullptr, *k16 = nullptr;
    cudaGetSymbolAddress((void**)&q16, g_q16);
    cudaGetSymbolAddress((void**)&k16, g_k16);
    cudaFuncSetAttribute(proj_all_kernel, cudaFuncAttributeMaxDynamicSharedMemorySize, PROJ_SMEM);
    cudaFuncSetAttribute(attn_kernel, cudaFuncAttributeMaxDynamicSharedMemorySize, ATTN_SMEM);

    dim3 pgrid(HWP / 128, BB, 2);
    proj_all_kernel<<<pgrid, 256, PROJ_SMEM>>>(lidar_x, lw, lg, lb, lm, lv,
                                               image_x, iw, ig, ib, im, iv,
                                               q16, k16);

    dim3 agrid(CHUNKP / 128, NCHUNK, BB);
    attn_kernel<<<agrid, 256, ATTN_SMEM>>>(q16, k16, mw, out);
}